// round 5
// baseline (speedup 1.0000x reference)
#include <cuda_runtime.h>
#include <cuda_fp16.h>
#include <cstdint>

// ---------------------------------------------------------------------------
// SAGE_37203006718147: 3-layer GraphSAGE on sm_103a.
// Per layer: fused kernel (edge aggregation CTAs + self-GEMM CTAs interleaved
// in one grid -> DRAM-bound and tensor-bound work co-run), then a neigh-GEMM
// that accumulates (agg/deg)@Wn into the partial output.
// GEMM: mma.sync fp16 2-term split (C = Ah*B + Al*B). tcgen05 unavailable
// (harness compiles at virtual arch compute_103, no 'a').
// ---------------------------------------------------------------------------

#define N1C 50000
#define N2C 12000
#define N3C 3000
#define DF  256

// ---- scratch (static device allocations; cudaMalloc forbidden) ----
__device__ float g_agg0[N1C * DF];
__device__ float g_deg0[N1C];
__device__ float g_h1  [N1C * DF];
__device__ float g_agg1[N2C * DF];
__device__ float g_deg1[N2C];
__device__ float g_h2  [N2C * DF];
__device__ float g_agg2[N3C * DF];
__device__ float g_deg2[N3C];
// transposed fp16 weights: [N][K=512] = [Ws ; Wn], K-major
__device__ __half g_wt0[256 * 512];
__device__ __half g_wt1[256 * 512];
__device__ __half g_wt2[64 * 512];

// ---------------------------------------------------------------------------
// helpers
// ---------------------------------------------------------------------------
__device__ __forceinline__ uint32_t smem_u32(const void* p) {
    uint32_t a;
    asm("{ .reg .u64 t; cvta.to.shared.u64 t, %1; cvt.u32.u64 %0, t; }"
        : "=r"(a) : "l"(p));
    return a;
}

__device__ __forceinline__ void ldsm4(uint32_t* r, uint32_t addr) {
    asm volatile("ldmatrix.sync.aligned.m8n8.x4.shared.b16 {%0,%1,%2,%3}, [%4];"
                 : "=r"(r[0]), "=r"(r[1]), "=r"(r[2]), "=r"(r[3]) : "r"(addr));
}

__device__ __forceinline__ void mma16816(float* c, const uint32_t* a,
                                         const uint32_t* b) {
    asm volatile(
        "mma.sync.aligned.m16n8k16.row.col.f32.f16.f16.f32 "
        "{%0,%1,%2,%3}, {%4,%5,%6,%7}, {%8,%9}, {%0,%1,%2,%3};"
        : "+f"(c[0]), "+f"(c[1]), "+f"(c[2]), "+f"(c[3])
        : "r"(a[0]), "r"(a[1]), "r"(a[2]), "r"(a[3]), "r"(b[0]), "r"(b[1]));
}

// split 8 fp32 -> 8 fp16 hi + 8 fp16 lo (packed as uint4 each)
__device__ __forceinline__ void split8(float4 a, float4 b, uint4& hi, uint4& lo) {
    float f[8] = {a.x, a.y, a.z, a.w, b.x, b.y, b.z, b.w};
    uint32_t H[8], L[8];
#pragma unroll
    for (int i = 0; i < 8; i++) {
        __half h = __float2half_rn(f[i]);
        float r = f[i] - __half2float(h);
        __half l = __float2half_rn(r);
        H[i] = (uint32_t)__half_as_ushort(h);
        L[i] = (uint32_t)__half_as_ushort(l);
    }
    hi.x = H[0] | (H[1] << 16); hi.y = H[2] | (H[3] << 16);
    hi.z = H[4] | (H[5] << 16); hi.w = H[6] | (H[7] << 16);
    lo.x = L[0] | (L[1] << 16); lo.y = L[2] | (L[3] << 16);
    lo.z = L[4] | (L[5] << 16); lo.w = L[6] | (L[7] << 16);
}

// ---------------------------------------------------------------------------
// Weight prep: Wt[n][k] = fp16(k<256 ? Ws[k][n] : Wn[k-256][n]), K-major
// ---------------------------------------------------------------------------
__global__ void convert_weights(const float* __restrict__ Ws,
                                const float* __restrict__ Wn,
                                __half* __restrict__ wt, int NC)
{
    int idx = blockIdx.x * blockDim.x + threadIdx.x;
    if (idx >= NC * 512) return;
    int n = idx >> 9, k = idx & 511;
    float v = (k < 256) ? Ws[(size_t)k * NC + n] : Wn[(size_t)(k - 256) * NC + n];
    wt[idx] = __float2half_rn(v);
}

// ---------------------------------------------------------------------------
// GEMM tile (device fn): out[bm0:+128, bn0:+BN] for K=256.
//   NEIGH: A scaled by 1/max(deg,1); accumulate into existing out; opt. RELU.
//   !NEIGH: plain A; write acc + bias.
// 8 warps (4x2), warp tile 32x(BN/2), BK=32, double-buffered cp.async for B,
// A staged fp32->fp16 hi/lo through registers. 2-term HMMA.
// ---------------------------------------------------------------------------
template<int BN, bool NEIGH, bool RELU>
__device__ __forceinline__ void gemm_tile(
    const float* __restrict__ A, const float* __restrict__ deg,
    const __half* __restrict__ wt, int koff,
    const float* __restrict__ bias, float* __restrict__ out,
    int M, int NCOLS, int bm0, int bn0, char* smem)
{
    constexpr int APITCH = 80;            // bytes/smem row (64B data + 16 pad)
    constexpr int ASTG   = 128 * APITCH;  // per A matrix
    constexpr int BSTG   = BN * APITCH;   // B matrix
    constexpr int SS     = 2 * ASTG + BSTG;
    constexpr int NT8    = BN / 16;
    constexpr int NBSEG  = (BN * 4) / 256;
    constexpr int WN     = BN / 2;

    float* s_invd = (float*)smem;
    char*  stg    = smem + 1024;
    uint32_t stg_u = smem_u32(stg);

    int tid  = threadIdx.x;
    int lane = tid & 31, wid = tid >> 5;
    int wm = wid & 3, wn = wid >> 2;

    if (NEIGH) {
        if (tid < 128) {
            int r = bm0 + tid;
            float dg = (r < M) ? deg[r] : 1.0f;
            s_invd[tid] = 1.0f / fmaxf(dg, 1.0f);
        }
        __syncthreads();
    }

    uint4 ah[2], al[2];

    auto prepA = [&](int kt) {
        int kc = kt * 32;
#pragma unroll
        for (int i = 0; i < 2; i++) {
            int seg = tid + 256 * i;          // 0..511
            int row = seg >> 2, c8 = (seg & 3) * 8;
            int gr = bm0 + row;
            float4 v0 = make_float4(0.f, 0.f, 0.f, 0.f), v1 = v0;
            if (gr < M) {
                const float4* p = (const float4*)(A + (size_t)gr * DF + kc + c8);
                v0 = __ldg(p); v1 = __ldg(p + 1);
                if (NEIGH) {
                    float sc = s_invd[row];
                    v0.x *= sc; v0.y *= sc; v0.z *= sc; v0.w *= sc;
                    v1.x *= sc; v1.y *= sc; v1.z *= sc; v1.w *= sc;
                }
            }
            split8(v0, v1, ah[i], al[i]);
        }
    };

    auto storeA = [&](int s) {
        char* base = stg + s * SS;
#pragma unroll
        for (int i = 0; i < 2; i++) {
            int seg = tid + 256 * i;
            int row = seg >> 2, cc = (seg & 3) * 16;
            *(uint4*)(base + row * APITCH + cc)        = ah[i];
            *(uint4*)(base + ASTG + row * APITCH + cc) = al[i];
        }
    };

    auto issueB = [&](int kt, int s) {
        int kg = kt * 32;
        uint32_t bbase = stg_u + s * SS + 2 * ASTG;
#pragma unroll
        for (int i = 0; i < NBSEG; i++) {
            int seg = tid + 256 * i;
            int row = seg >> 2, cc = (seg & 3) * 16;
            uint32_t sa = bbase + row * APITCH + cc;
            const __half* g = wt + (size_t)(bn0 + row) * 512 + koff + kg + (seg & 3) * 8;
            asm volatile("cp.async.cg.shared.global [%0], [%1], 16;"
                         :: "r"(sa), "l"(g));
        }
        asm volatile("cp.async.commit_group;" ::: "memory");
    };

    float acc[2][NT8][4] = {};

    issueB(0, 0);
    prepA(0);

#pragma unroll 1
    for (int kt = 0; kt < 8; kt++) {
        int s = kt & 1;
        storeA(s);
        asm volatile("cp.async.wait_group 0;" ::: "memory");
        __syncthreads();
        if (kt < 7) {
            issueB(kt + 1, 1 - s);
            prepA(kt + 1);
        }

        uint32_t abase = stg_u + s * SS;
        uint32_t bbase = abase + 2 * ASTG;
#pragma unroll
        for (int ks = 0; ks < 2; ks++) {
            uint32_t afh[2][4], afl[2][4], bf[NT8][2];
#pragma unroll
            for (int mt = 0; mt < 2; mt++) {
                int r  = wm * 32 + mt * 16 + (lane & 7) + ((lane >> 3) & 1) * 8;
                int kb = ks * 16 + ((lane >> 4) & 1) * 8;
                uint32_t ad = abase + r * APITCH + kb * 2;
                ldsm4(afh[mt], ad);
                ldsm4(afl[mt], ad + ASTG);
            }
#pragma unroll
            for (int p = 0; p < NT8 / 2; p++) {
                int n  = wn * WN + p * 16 + (lane & 7) + ((lane >> 4) & 1) * 8;
                int kb = ks * 16 + ((lane >> 3) & 1) * 8;
                uint32_t bd = bbase + n * APITCH + kb * 2;
                uint32_t th[4];
                ldsm4(th, bd);
                bf[2 * p][0] = th[0]; bf[2 * p][1] = th[1];
                bf[2 * p + 1][0] = th[2]; bf[2 * p + 1][1] = th[3];
            }
#pragma unroll
            for (int mt = 0; mt < 2; mt++)
#pragma unroll
                for (int nt = 0; nt < NT8; nt++) {
                    mma16816(acc[mt][nt], afh[mt], bf[nt]);
                    mma16816(acc[mt][nt], afl[mt], bf[nt]);
                }
        }
    }

    // ---- epilogue ----
#pragma unroll
    for (int mt = 0; mt < 2; mt++) {
        int r0 = bm0 + wm * 32 + mt * 16 + (lane >> 2);
#pragma unroll
        for (int nt = 0; nt < NT8; nt++) {
            int col = bn0 + wn * WN + nt * 8 + (lane & 3) * 2;
            float2 o0, o1;
            if (NEIGH) {
                o0.x = acc[mt][nt][0]; o0.y = acc[mt][nt][1];
                o1.x = acc[mt][nt][2]; o1.y = acc[mt][nt][3];
                if (r0 < M) {
                    float2 e = *(const float2*)(out + (size_t)r0 * NCOLS + col);
                    o0.x += e.x; o0.y += e.y;
                }
                if (r0 + 8 < M) {
                    float2 e = *(const float2*)(out + (size_t)(r0 + 8) * NCOLS + col);
                    o1.x += e.x; o1.y += e.y;
                }
                if (RELU) {
                    o0.x = fmaxf(o0.x, 0.f); o0.y = fmaxf(o0.y, 0.f);
                    o1.x = fmaxf(o1.x, 0.f); o1.y = fmaxf(o1.y, 0.f);
                }
            } else {
                float2 bv = *(const float2*)(bias + col);
                o0.x = acc[mt][nt][0] + bv.x; o0.y = acc[mt][nt][1] + bv.y;
                o1.x = acc[mt][nt][2] + bv.x; o1.y = acc[mt][nt][3] + bv.y;
            }
            if (r0 < M)
                *(float2*)(out + (size_t)r0 * NCOLS + col) = o0;
            if (r0 + 8 < M)
                *(float2*)(out + (size_t)(r0 + 8) * NCOLS + col) = o1;
        }
    }
}

// ---------------------------------------------------------------------------
// Fused kernel: agg CTAs + self-GEMM CTAs in one grid, interleaved every R
// blocks so both resource classes co-run. Agg role: 8 edges/warp, batched
// LDG.128 gather then vector red.global.add.
// ---------------------------------------------------------------------------
template<int BN>
__global__ __launch_bounds__(256)
void fused_agg_selfgemm(
    const float* __restrict__ h, const int* __restrict__ src,
    const int* __restrict__ dst, float* __restrict__ agg,
    float* __restrict__ deg, int E,
    const __half* __restrict__ wt, const float* __restrict__ bias,
    float* __restrict__ out, int M, int NCOLS, int nbn, int nGemm, int R)
{
    extern __shared__ char smem[];
    int b = blockIdx.x;
    int g = b / R;

    if ((b % R) == 0 && g < nGemm) {
        gemm_tile<BN, false, false>(h, nullptr, wt, 0, bias, out, M, NCOLS,
                                    (g / nbn) * 128, (g % nbn) * BN, smem);
        return;
    }

    // ---- aggregation role ----
    int before = (b == 0) ? 0 : min(nGemm, (b - 1) / R + 1);
    int ai = b - before;
    int warp = ai * 8 + (threadIdx.x >> 5);
    int lane = threadIdx.x & 31;
    int e0 = warp * 8;
    if (e0 >= E) return;
    int n = min(8, E - e0);

    int s[8], d[8];
#pragma unroll
    for (int e = 0; e < 8; e++) {
        int idx = (e < n) ? e0 + e : e0;
        s[e] = __ldg(src + idx);
        d[e] = __ldg(dst + idx);
    }
    float4 v[8][2];
#pragma unroll
    for (int e = 0; e < 8; e++) {
        if (e < n) {
            const float4* hs = (const float4*)(h + (size_t)s[e] * DF) + lane;
            v[e][0] = __ldg(hs);
            v[e][1] = __ldg(hs + 32);
        }
    }
#pragma unroll
    for (int e = 0; e < 8; e++) {
        if (e < n) {
            float* p = agg + (size_t)d[e] * DF + lane * 4;
            asm volatile("red.global.add.v4.f32 [%0], {%1, %2, %3, %4};"
                         :: "l"(p), "f"(v[e][0].x), "f"(v[e][0].y),
                            "f"(v[e][0].z), "f"(v[e][0].w) : "memory");
            asm volatile("red.global.add.v4.f32 [%0], {%1, %2, %3, %4};"
                         :: "l"(p + 128), "f"(v[e][1].x), "f"(v[e][1].y),
                            "f"(v[e][1].z), "f"(v[e][1].w) : "memory");
        }
    }
#pragma unroll
    for (int e = 0; e < 8; e++)
        if (lane == e && e < n) atomicAdd(deg + d[e], 1.0f);
}

// ---------------------------------------------------------------------------
// Neigh GEMM: out[bm, bn] += (agg/deg) @ Wn  (+relu)
// ---------------------------------------------------------------------------
template<int BN, bool RELU>
__global__ __launch_bounds__(256)
void sage_gemm_neigh(const float* __restrict__ agg,
                     const float* __restrict__ deg,
                     const __half* __restrict__ wt,
                     float* __restrict__ out, int M, int NCOLS)
{
    extern __shared__ char smem[];
    gemm_tile<BN, true, RELU>(agg, deg, wt, 256, nullptr, out, M, NCOLS,
                              blockIdx.y * 128, blockIdx.x * BN, smem);
}

// ---------------------------------------------------------------------------
// Launch
// ---------------------------------------------------------------------------
extern "C" void kernel_launch(void* const* d_in, const int* in_sizes, int n_in,
                              void* d_out, int out_size)
{
    const float* x    = (const float*)d_in[0];
    const int*   src0 = (const int*)d_in[1];
    const int*   dst0 = (const int*)d_in[2];
    const int*   src1 = (const int*)d_in[3];
    const int*   dst1 = (const int*)d_in[4];
    const int*   src2 = (const int*)d_in[5];
    const int*   dst2 = (const int*)d_in[6];

    int wb = n_in - 9;
    const float* Ws0 = (const float*)d_in[wb + 0];
    const float* Wn0 = (const float*)d_in[wb + 1];
    const float* b0  = (const float*)d_in[wb + 2];
    const float* Ws1 = (const float*)d_in[wb + 3];
    const float* Wn1 = (const float*)d_in[wb + 4];
    const float* b1  = (const float*)d_in[wb + 5];
    const float* Ws2 = (const float*)d_in[wb + 6];
    const float* Wn2 = (const float*)d_in[wb + 7];
    const float* b2  = (const float*)d_in[wb + 8];

    int E0 = in_sizes[1];
    int E1 = in_sizes[3];
    int E2 = in_sizes[5];

    float *agg0, *deg0, *h1, *agg1, *deg1, *h2, *agg2, *deg2;
    __half *wt0, *wt1, *wt2;
    cudaGetSymbolAddress((void**)&agg0, g_agg0);
    cudaGetSymbolAddress((void**)&deg0, g_deg0);
    cudaGetSymbolAddress((void**)&h1,   g_h1);
    cudaGetSymbolAddress((void**)&agg1, g_agg1);
    cudaGetSymbolAddress((void**)&deg1, g_deg1);
    cudaGetSymbolAddress((void**)&h2,   g_h2);
    cudaGetSymbolAddress((void**)&agg2, g_agg2);
    cudaGetSymbolAddress((void**)&deg2, g_deg2);
    cudaGetSymbolAddress((void**)&wt0,  g_wt0);
    cudaGetSymbolAddress((void**)&wt1,  g_wt1);
    cudaGetSymbolAddress((void**)&wt2,  g_wt2);

    const int SMEM128 = 1024 + 2 * (2 * 128 * 80 + 128 * 80);  // 62464
    const int SMEM64  = 1024 + 2 * (2 * 128 * 80 + 64 * 80);   // 52224
    cudaFuncSetAttribute(fused_agg_selfgemm<128>,
                         cudaFuncAttributeMaxDynamicSharedMemorySize, SMEM128);
    cudaFuncSetAttribute(fused_agg_selfgemm<64>,
                         cudaFuncAttributeMaxDynamicSharedMemorySize, SMEM64);
    cudaFuncSetAttribute(sage_gemm_neigh<128, false>,
                         cudaFuncAttributeMaxDynamicSharedMemorySize, SMEM128);
    cudaFuncSetAttribute(sage_gemm_neigh<128, true>,
                         cudaFuncAttributeMaxDynamicSharedMemorySize, SMEM128);
    cudaFuncSetAttribute(sage_gemm_neigh<64, false>,
                         cudaFuncAttributeMaxDynamicSharedMemorySize, SMEM64);

    // ---- prep: weights + zero scratch ----
    convert_weights<<<(256 * 512 + 255) / 256, 256>>>(Ws0, Wn0, wt0, 256);
    convert_weights<<<(256 * 512 + 255) / 256, 256>>>(Ws1, Wn1, wt1, 256);
    convert_weights<<<(64  * 512 + 255) / 256, 256>>>(Ws2, Wn2, wt2, 64);
    cudaMemsetAsync(agg0, 0, sizeof(float) * (size_t)N1C * DF);
    cudaMemsetAsync(deg0, 0, sizeof(float) * N1C);
    cudaMemsetAsync(agg1, 0, sizeof(float) * (size_t)N2C * DF);
    cudaMemsetAsync(deg1, 0, sizeof(float) * N2C);
    cudaMemsetAsync(agg2, 0, sizeof(float) * (size_t)N3C * DF);
    cudaMemsetAsync(deg2, 0, sizeof(float) * N3C);

    // ---- Layer 0: x -> h1 (N1 x 256) ----
    {
        int nAgg = (E0 + 63) / 64;
        int nbn = 2, nGemm = nbn * ((N1C + 127) / 128);
        int total = nAgg + nGemm;
        int R = total / nGemm; if (R < 1) R = 1;
        fused_agg_selfgemm<128><<<total, 256, SMEM128>>>(
            x, src0, dst0, agg0, deg0, E0, wt0, b0, h1, N1C, 256, nbn, nGemm, R);
        sage_gemm_neigh<128, false><<<dim3(2, (N1C + 127) / 128), 256, SMEM128>>>(
            agg0, deg0, wt0, h1, N1C, 256);
    }

    // ---- Layer 1: h1 -> h2 (N2 x 256), relu ----
    {
        int nAgg = (E1 + 63) / 64;
        int nbn = 2, nGemm = nbn * ((N2C + 127) / 128);
        int total = nAgg + nGemm;
        int R = total / nGemm; if (R < 1) R = 1;
        fused_agg_selfgemm<128><<<total, 256, SMEM128>>>(
            h1, src1, dst1, agg1, deg1, E1, wt1, b1, h2, N2C, 256, nbn, nGemm, R);
        sage_gemm_neigh<128, true><<<dim3(2, (N2C + 127) / 128), 256, SMEM128>>>(
            agg1, deg1, wt1, h2, N2C, 256);
    }

    // ---- Layer 2: h2 -> out (N3 x 64) ----
    {
        int nAgg = (E2 + 63) / 64;
        int nbn = 1, nGemm = (N3C + 127) / 128;
        int total = nAgg + nGemm;
        int R = total / nGemm; if (R < 1) R = 1;
        fused_agg_selfgemm<64><<<total, 256, SMEM64>>>(
            h2, src2, dst2, agg2, deg2, E2, wt2, b2, (float*)d_out, N3C, 64,
            nbn, nGemm, R);
        sage_gemm_neigh<64, false><<<dim3(1, (N3C + 127) / 128), 256, SMEM64>>>(
            agg2, deg2, wt2, (float*)d_out, N3C, 64);
    }
}

// round 6
// speedup vs baseline: 1.3491x; 1.3491x over previous
#include <cuda_runtime.h>
#include <cuda_fp16.h>
#include <cstdint>

// ---------------------------------------------------------------------------
// SAGE_37203006718147: 3-layer GraphSAGE on sm_103a.
// Structure per layer (fork-join captured as parallel graph branches):
//   [default] edge-aggregation   ||  [stream2] self-GEMM (h@Ws + b)
//   join -> [default] neigh-GEMM: out += (agg/deg)@Wn (+relu)
// GEMM: mma.sync fp16 1-term (A,B both fp16-quantized; fp32 accumulate).
// tcgen05 unavailable: harness compiles at virtual arch compute_103 (no 'a').
// ---------------------------------------------------------------------------

#define N1C 50000
#define N2C 12000
#define N3C 3000
#define DF  256

// ---- scratch (static device allocations; cudaMalloc forbidden) ----
__device__ float g_agg0[N1C * DF];
__device__ float g_deg0[N1C];
__device__ float g_h1  [N1C * DF];
__device__ float g_agg1[N2C * DF];
__device__ float g_deg1[N2C];
__device__ float g_h2  [N2C * DF];
__device__ float g_agg2[N3C * DF];
__device__ float g_deg2[N3C];
// transposed fp16 weights: [N][K=512] = [Ws ; Wn], K-major
__device__ __half g_wt0[256 * 512];
__device__ __half g_wt1[256 * 512];
__device__ __half g_wt2[64 * 512];

// ---------------------------------------------------------------------------
// helpers
// ---------------------------------------------------------------------------
__device__ __forceinline__ uint32_t smem_u32(const void* p) {
    uint32_t a;
    asm("{ .reg .u64 t; cvta.to.shared.u64 t, %1; cvt.u32.u64 %0, t; }"
        : "=r"(a) : "l"(p));
    return a;
}

__device__ __forceinline__ void ldsm4(uint32_t* r, uint32_t addr) {
    asm volatile("ldmatrix.sync.aligned.m8n8.x4.shared.b16 {%0,%1,%2,%3}, [%4];"
                 : "=r"(r[0]), "=r"(r[1]), "=r"(r[2]), "=r"(r[3]) : "r"(addr));
}

__device__ __forceinline__ void mma16816(float* c, const uint32_t* a,
                                         const uint32_t* b) {
    asm volatile(
        "mma.sync.aligned.m16n8k16.row.col.f32.f16.f16.f32 "
        "{%0,%1,%2,%3}, {%4,%5,%6,%7}, {%8,%9}, {%0,%1,%2,%3};"
        : "+f"(c[0]), "+f"(c[1]), "+f"(c[2]), "+f"(c[3])
        : "r"(a[0]), "r"(a[1]), "r"(a[2]), "r"(a[3]), "r"(b[0]), "r"(b[1]));
}

// convert 8 fp32 -> 8 packed fp16 (uint4)
__device__ __forceinline__ uint4 cvt8(float4 a, float4 b) {
    float f[8] = {a.x, a.y, a.z, a.w, b.x, b.y, b.z, b.w};
    uint32_t H[8];
#pragma unroll
    for (int i = 0; i < 8; i++)
        H[i] = (uint32_t)__half_as_ushort(__float2half_rn(f[i]));
    uint4 r;
    r.x = H[0] | (H[1] << 16); r.y = H[2] | (H[3] << 16);
    r.z = H[4] | (H[5] << 16); r.w = H[6] | (H[7] << 16);
    return r;
}

// ---------------------------------------------------------------------------
// Weight prep: Wt[n][k] = fp16(k<256 ? Ws[k][n] : Wn[k-256][n]), K-major
// ---------------------------------------------------------------------------
__global__ void convert_weights(const float* __restrict__ Ws,
                                const float* __restrict__ Wn,
                                __half* __restrict__ wt, int NC)
{
    int idx = blockIdx.x * blockDim.x + threadIdx.x;
    if (idx >= NC * 512) return;
    int n = idx >> 9, k = idx & 511;
    float v = (k < 256) ? Ws[(size_t)k * NC + n] : Wn[(size_t)(k - 256) * NC + n];
    wt[idx] = __float2half_rn(v);
}

// ---------------------------------------------------------------------------
// Edge aggregation: 4 edges per warp, batched LDG.128 then vector REDs
// ---------------------------------------------------------------------------
__global__ void sage_aggregate(const float* __restrict__ h,
                               const int*   __restrict__ src,
                               const int*   __restrict__ dst,
                               float*       __restrict__ agg,
                               float*       __restrict__ deg,
                               int E)
{
    int warp = (int)(blockIdx.x * (blockDim.x >> 5) + (threadIdx.x >> 5));
    int lane = threadIdx.x & 31;
    int e0 = warp * 4;
    if (e0 >= E) return;
    int n = E - e0;
    if (n > 4) n = 4;

    int s[4], d[4];
#pragma unroll
    for (int e = 0; e < 4; e++) {
        int idx = (e < n) ? e0 + e : e0;
        s[e] = __ldg(src + idx);
        d[e] = __ldg(dst + idx);
    }
    float4 v[4][2];
#pragma unroll
    for (int e = 0; e < 4; e++) {
        if (e < n) {
            const float4* hs = (const float4*)(h + (size_t)s[e] * DF) + lane;
            v[e][0] = __ldg(hs);
            v[e][1] = __ldg(hs + 32);
        }
    }
#pragma unroll
    for (int e = 0; e < 4; e++) {
        if (e < n) {
            float* p = agg + (size_t)d[e] * DF + lane * 4;
            asm volatile("red.global.add.v4.f32 [%0], {%1, %2, %3, %4};"
                         :: "l"(p), "f"(v[e][0].x), "f"(v[e][0].y),
                            "f"(v[e][0].z), "f"(v[e][0].w) : "memory");
            asm volatile("red.global.add.v4.f32 [%0], {%1, %2, %3, %4};"
                         :: "l"(p + 128), "f"(v[e][1].x), "f"(v[e][1].y),
                            "f"(v[e][1].z), "f"(v[e][1].w) : "memory");
        }
    }
#pragma unroll
    for (int e = 0; e < 4; e++)
        if (lane == e && e < n) atomicAdd(deg + d[e], 1.0f);
}

// ---------------------------------------------------------------------------
// GEMM tile (device fn), K=256 slice of the [Ws;Wn] weight:
//   NEIGH: A scaled by 1/max(deg,1); accumulate into out; optional RELU.
//   !NEIGH: plain A; write acc + bias.
// 8 warps (4x2), warp tile 32x(BN/2), BK=32, double-buffered cp.async for B,
// A staged fp32 -> fp16 through registers. 1-term HMMA.
// ---------------------------------------------------------------------------
template<int BN, bool NEIGH, bool RELU>
__device__ __forceinline__ void gemm_tile(
    const float* __restrict__ A, const float* __restrict__ deg,
    const __half* __restrict__ wt, int koff,
    const float* __restrict__ bias, float* __restrict__ out,
    int M, int NCOLS, int bm0, int bn0, char* smem)
{
    constexpr int APITCH = 80;            // bytes/smem row (64B data + 16 pad)
    constexpr int ASTG   = 128 * APITCH;  // A matrix
    constexpr int BSTG   = BN * APITCH;   // B matrix
    constexpr int SS     = ASTG + BSTG;
    constexpr int NT8    = BN / 16;
    constexpr int NBSEG  = (BN * 4) / 256;
    constexpr int WN     = BN / 2;

    float* s_invd = (float*)smem;
    char*  stg    = smem + 1024;
    uint32_t stg_u = smem_u32(stg);

    int tid  = threadIdx.x;
    int lane = tid & 31, wid = tid >> 5;
    int wm = wid & 3, wn = wid >> 2;

    if (NEIGH) {
        if (tid < 128) {
            int r = bm0 + tid;
            float dg = (r < M) ? deg[r] : 1.0f;
            s_invd[tid] = 1.0f / fmaxf(dg, 1.0f);
        }
        __syncthreads();
    }

    uint4 ah[2];

    auto prepA = [&](int kt) {
        int kc = kt * 32;
#pragma unroll
        for (int i = 0; i < 2; i++) {
            int seg = tid + 256 * i;          // 0..511
            int row = seg >> 2, c8 = (seg & 3) * 8;
            int gr = bm0 + row;
            float4 v0 = make_float4(0.f, 0.f, 0.f, 0.f), v1 = v0;
            if (gr < M) {
                const float4* p = (const float4*)(A + (size_t)gr * DF + kc + c8);
                v0 = __ldg(p); v1 = __ldg(p + 1);
                if (NEIGH) {
                    float sc = s_invd[row];
                    v0.x *= sc; v0.y *= sc; v0.z *= sc; v0.w *= sc;
                    v1.x *= sc; v1.y *= sc; v1.z *= sc; v1.w *= sc;
                }
            }
            ah[i] = cvt8(v0, v1);
        }
    };

    auto storeA = [&](int s) {
        char* base = stg + s * SS;
#pragma unroll
        for (int i = 0; i < 2; i++) {
            int seg = tid + 256 * i;
            int row = seg >> 2, cc = (seg & 3) * 16;
            *(uint4*)(base + row * APITCH + cc) = ah[i];
        }
    };

    auto issueB = [&](int kt, int s) {
        int kg = kt * 32;
        uint32_t bbase = stg_u + s * SS + ASTG;
#pragma unroll
        for (int i = 0; i < NBSEG; i++) {
            int seg = tid + 256 * i;
            int row = seg >> 2, cc = (seg & 3) * 16;
            uint32_t sa = bbase + row * APITCH + cc;
            const __half* g = wt + (size_t)(bn0 + row) * 512 + koff + kg + (seg & 3) * 8;
            asm volatile("cp.async.cg.shared.global [%0], [%1], 16;"
                         :: "r"(sa), "l"(g));
        }
        asm volatile("cp.async.commit_group;" ::: "memory");
    };

    float acc[2][NT8][4] = {};

    issueB(0, 0);
    prepA(0);

#pragma unroll 1
    for (int kt = 0; kt < 8; kt++) {
        int s = kt & 1;
        storeA(s);
        asm volatile("cp.async.wait_group 0;" ::: "memory");
        __syncthreads();
        if (kt < 7) {
            issueB(kt + 1, 1 - s);
            prepA(kt + 1);
        }

        uint32_t abase = stg_u + s * SS;
        uint32_t bbase = abase + ASTG;
#pragma unroll
        for (int ks = 0; ks < 2; ks++) {
            uint32_t af[2][4], bf[NT8][2];
#pragma unroll
            for (int mt = 0; mt < 2; mt++) {
                int r  = wm * 32 + mt * 16 + (lane & 7) + ((lane >> 3) & 1) * 8;
                int kb = ks * 16 + ((lane >> 4) & 1) * 8;
                ldsm4(af[mt], abase + r * APITCH + kb * 2);
            }
#pragma unroll
            for (int p = 0; p < NT8 / 2; p++) {
                int n  = wn * WN + p * 16 + (lane & 7) + ((lane >> 4) & 1) * 8;
                int kb = ks * 16 + ((lane >> 3) & 1) * 8;
                uint32_t th[4];
                ldsm4(th, bbase + n * APITCH + kb * 2);
                bf[2 * p][0] = th[0]; bf[2 * p][1] = th[1];
                bf[2 * p + 1][0] = th[2]; bf[2 * p + 1][1] = th[3];
            }
#pragma unroll
            for (int mt = 0; mt < 2; mt++)
#pragma unroll
                for (int nt = 0; nt < NT8; nt++)
                    mma16816(acc[mt][nt], af[mt], bf[nt]);
        }
    }

    // ---- epilogue ----
#pragma unroll
    for (int mt = 0; mt < 2; mt++) {
        int r0 = bm0 + wm * 32 + mt * 16 + (lane >> 2);
#pragma unroll
        for (int nt = 0; nt < NT8; nt++) {
            int col = bn0 + wn * WN + nt * 8 + (lane & 3) * 2;
            float2 o0, o1;
            if (NEIGH) {
                o0.x = acc[mt][nt][0]; o0.y = acc[mt][nt][1];
                o1.x = acc[mt][nt][2]; o1.y = acc[mt][nt][3];
                if (r0 < M) {
                    float2 e = *(const float2*)(out + (size_t)r0 * NCOLS + col);
                    o0.x += e.x; o0.y += e.y;
                }
                if (r0 + 8 < M) {
                    float2 e = *(const float2*)(out + (size_t)(r0 + 8) * NCOLS + col);
                    o1.x += e.x; o1.y += e.y;
                }
                if (RELU) {
                    o0.x = fmaxf(o0.x, 0.f); o0.y = fmaxf(o0.y, 0.f);
                    o1.x = fmaxf(o1.x, 0.f); o1.y = fmaxf(o1.y, 0.f);
                }
            } else {
                float2 bv = *(const float2*)(bias + col);
                o0.x = acc[mt][nt][0] + bv.x; o0.y = acc[mt][nt][1] + bv.y;
                o1.x = acc[mt][nt][2] + bv.x; o1.y = acc[mt][nt][3] + bv.y;
            }
            if (r0 < M)
                *(float2*)(out + (size_t)r0 * NCOLS + col) = o0;
            if (r0 + 8 < M)
                *(float2*)(out + (size_t)(r0 + 8) * NCOLS + col) = o1;
        }
    }
}

template<int BN>
__global__ __launch_bounds__(256)
void sage_gemm_self(const float* __restrict__ h,
                    const __half* __restrict__ wt,
                    const float* __restrict__ bias,
                    float* __restrict__ out, int M, int NCOLS)
{
    extern __shared__ char smem[];
    gemm_tile<BN, false, false>(h, nullptr, wt, 0, bias, out, M, NCOLS,
                                blockIdx.y * 128, blockIdx.x * BN, smem);
}

template<int BN, bool RELU>
__global__ __launch_bounds__(256)
void sage_gemm_neigh(const float* __restrict__ agg,
                     const float* __restrict__ deg,
                     const __half* __restrict__ wt,
                     float* __restrict__ out, int M, int NCOLS)
{
    extern __shared__ char smem[];
    gemm_tile<BN, true, RELU>(agg, deg, wt, 256, nullptr, out, M, NCOLS,
                              blockIdx.y * 128, blockIdx.x * BN, smem);
}

// ---------------------------------------------------------------------------
// Launch: fork-join per layer (agg on default stream || self-GEMM on s2)
// ---------------------------------------------------------------------------
extern "C" void kernel_launch(void* const* d_in, const int* in_sizes, int n_in,
                              void* d_out, int out_size)
{
    const float* x    = (const float*)d_in[0];
    const int*   src0 = (const int*)d_in[1];
    const int*   dst0 = (const int*)d_in[2];
    const int*   src1 = (const int*)d_in[3];
    const int*   dst1 = (const int*)d_in[4];
    const int*   src2 = (const int*)d_in[5];
    const int*   dst2 = (const int*)d_in[6];

    int wb = n_in - 9;
    const float* Ws0 = (const float*)d_in[wb + 0];
    const float* Wn0 = (const float*)d_in[wb + 1];
    const float* b0  = (const float*)d_in[wb + 2];
    const float* Ws1 = (const float*)d_in[wb + 3];
    const float* Wn1 = (const float*)d_in[wb + 4];
    const float* b1  = (const float*)d_in[wb + 5];
    const float* Ws2 = (const float*)d_in[wb + 6];
    const float* Wn2 = (const float*)d_in[wb + 7];
    const float* b2  = (const float*)d_in[wb + 8];

    int E0 = in_sizes[1];
    int E1 = in_sizes[3];
    int E2 = in_sizes[5];

    float *agg0, *deg0, *h1, *agg1, *deg1, *h2, *agg2, *deg2;
    __half *wt0, *wt1, *wt2;
    cudaGetSymbolAddress((void**)&agg0, g_agg0);
    cudaGetSymbolAddress((void**)&deg0, g_deg0);
    cudaGetSymbolAddress((void**)&h1,   g_h1);
    cudaGetSymbolAddress((void**)&agg1, g_agg1);
    cudaGetSymbolAddress((void**)&deg1, g_deg1);
    cudaGetSymbolAddress((void**)&h2,   g_h2);
    cudaGetSymbolAddress((void**)&agg2, g_agg2);
    cudaGetSymbolAddress((void**)&deg2, g_deg2);
    cudaGetSymbolAddress((void**)&wt0,  g_wt0);
    cudaGetSymbolAddress((void**)&wt1,  g_wt1);
    cudaGetSymbolAddress((void**)&wt2,  g_wt2);

    const int SMEM128 = 1024 + 2 * (128 * 80 + 128 * 80);  // 41984
    const int SMEM64  = 1024 + 2 * (128 * 80 + 64 * 80);   // 31744
    cudaFuncSetAttribute(sage_gemm_self<128>,
                         cudaFuncAttributeMaxDynamicSharedMemorySize, SMEM128);
    cudaFuncSetAttribute(sage_gemm_self<64>,
                         cudaFuncAttributeMaxDynamicSharedMemorySize, SMEM64);
    cudaFuncSetAttribute(sage_gemm_neigh<128, false>,
                         cudaFuncAttributeMaxDynamicSharedMemorySize, SMEM128);
    cudaFuncSetAttribute(sage_gemm_neigh<128, true>,
                         cudaFuncAttributeMaxDynamicSharedMemorySize, SMEM128);
    cudaFuncSetAttribute(sage_gemm_neigh<64, false>,
                         cudaFuncAttributeMaxDynamicSharedMemorySize, SMEM64);

    // side stream + fork/join events (created per call; only the capture call
    // and the one correctness call ever execute this — graph replays don't)
    cudaStream_t s2;
    cudaStreamCreateWithFlags(&s2, cudaStreamNonBlocking);
    cudaEvent_t evF[3], evJ[3];
    for (int i = 0; i < 3; i++) {
        cudaEventCreateWithFlags(&evF[i], cudaEventDisableTiming);
        cudaEventCreateWithFlags(&evJ[i], cudaEventDisableTiming);
    }

    // ---- prep: weights + zero scratch (default stream) ----
    convert_weights<<<(256 * 512 + 255) / 256, 256>>>(Ws0, Wn0, wt0, 256);
    convert_weights<<<(256 * 512 + 255) / 256, 256>>>(Ws1, Wn1, wt1, 256);
    convert_weights<<<(64  * 512 + 255) / 256, 256>>>(Ws2, Wn2, wt2, 64);
    cudaMemsetAsync(agg0, 0, sizeof(float) * (size_t)N1C * DF);
    cudaMemsetAsync(deg0, 0, sizeof(float) * N1C);
    cudaMemsetAsync(agg1, 0, sizeof(float) * (size_t)N2C * DF);
    cudaMemsetAsync(deg1, 0, sizeof(float) * N2C);
    cudaMemsetAsync(agg2, 0, sizeof(float) * (size_t)N3C * DF);
    cudaMemsetAsync(deg2, 0, sizeof(float) * N3C);

    // ---- Layer 0: x -> h1 (N1 x 256) ----
    cudaEventRecord(evF[0], 0);
    cudaStreamWaitEvent(s2, evF[0], 0);
    sage_aggregate<<<(E0 + 31) / 32, 256>>>(x, src0, dst0, agg0, deg0, E0);
    sage_gemm_self<128><<<dim3(2, (N1C + 127) / 128), 256, SMEM128, s2>>>(
        x, wt0, b0, h1, N1C, 256);
    cudaEventRecord(evJ[0], s2);
    cudaStreamWaitEvent(0, evJ[0], 0);
    sage_gemm_neigh<128, false><<<dim3(2, (N1C + 127) / 128), 256, SMEM128>>>(
        agg0, deg0, wt0, h1, N1C, 256);

    // ---- Layer 1: h1 -> h2 (N2 x 256), relu ----
    cudaEventRecord(evF[1], 0);
    cudaStreamWaitEvent(s2, evF[1], 0);
    sage_aggregate<<<(E1 + 31) / 32, 256>>>(h1, src1, dst1, agg1, deg1, E1);
    sage_gemm_self<128><<<dim3(2, (N2C + 127) / 128), 256, SMEM128, s2>>>(
        h1, wt1, b1, h2, N2C, 256);
    cudaEventRecord(evJ[1], s2);
    cudaStreamWaitEvent(0, evJ[1], 0);
    sage_gemm_neigh<128, true><<<dim3(2, (N2C + 127) / 128), 256, SMEM128>>>(
        agg1, deg1, wt1, h2, N2C, 256);

    // ---- Layer 2: h2 -> out (N3 x 64) ----
    cudaEventRecord(evF[2], 0);
    cudaStreamWaitEvent(s2, evF[2], 0);
    sage_aggregate<<<(E2 + 31) / 32, 256>>>(h2, src2, dst2, agg2, deg2, E2);
    sage_gemm_self<64><<<dim3(1, (N3C + 127) / 128), 256, SMEM64, s2>>>(
        h2, wt2, b2, (float*)d_out, N3C, 64);
    cudaEventRecord(evJ[2], s2);
    cudaStreamWaitEvent(0, evJ[2], 0);
    sage_gemm_neigh<64, false><<<dim3(1, (N3C + 127) / 128), 256, SMEM64>>>(
        agg2, deg2, wt2, (float*)d_out, N3C, 64);
}